// round 1
// baseline (speedup 1.0000x reference)
#include <cuda_runtime.h>
#include <math.h>
#include <stdint.h>

#define NN  50000
#define FF  256
#define HH  128
#define CC  16
#define HXD 64
#define EE  500000

// ---------------- scratch (device globals; no allocation allowed) ----------------
__device__ float g_xw1 [(size_t)NN * HH];   // x @ W1
__device__ float g_xe  [(size_t)NN * HXD];  // relu(x @ Wx + bx)
__device__ float g_agg1[(size_t)NN * HH];   // layer-1 aggregate -> h (relu in place)
__device__ float g_xw2 [(size_t)NN * CC];   // h @ W2
__device__ float g_agg2[(size_t)NN * CC];   // layer-2 aggregate = logits
__device__ float g_deg [NN];
__device__ float g_dinv[NN];
__device__ float g_norm[EE];
__device__ float g_u   [NN];
__device__ float g_v   [NN];
__device__ int   g_maskkind;                // 0=int32, 1=float32, 2=byte/bool

// ---------------- train_mask dtype detection ----------------
__global__ void detect_mask_kernel(const unsigned* tm) {
    __shared__ int bad_int, bad_float;
    if (threadIdx.x == 0) { bad_int = 0; bad_float = 0; }
    __syncthreads();
    for (int i = threadIdx.x; i < 2048; i += blockDim.x) {
        unsigned v = tm[i];
        if (v > 1u) atomicOr(&bad_int, 1);
        if (v != 0u && v != 0x3F800000u) atomicOr(&bad_float, 1);
    }
    __syncthreads();
    if (threadIdx.x == 0)
        g_maskkind = (bad_int == 0) ? 0 : ((bad_float == 0) ? 1 : 2);
}

// ---------------- degree / norm ----------------
__global__ void deg_init_kernel() {
    int i = blockIdx.x * blockDim.x + threadIdx.x;
    if (i < NN) g_deg[i] = 1.0f;   // self-loop
}
__global__ void deg_count_kernel(const int* __restrict__ dst) {
    int e = blockIdx.x * blockDim.x + threadIdx.x;
    if (e < EE) atomicAdd(&g_deg[dst[e]], 1.0f);
}
__global__ void dinv_kernel() {
    int i = blockIdx.x * blockDim.x + threadIdx.x;
    if (i < NN) g_dinv[i] = rsqrtf(g_deg[i]);
}
__global__ void norm_kernel(const int* __restrict__ src, const int* __restrict__ dst) {
    int e = blockIdx.x * blockDim.x + threadIdx.x;
    if (e < EE) g_norm[e] = g_dinv[src[e]] * g_dinv[dst[e]];
}

// ---------------- tiled fp32 GEMM: C[M,N] = A[M,K] @ B[K,N] (+bias, relu opt) ----------------
template <int BM, int BN, int BK, int TM, int TN>
__global__ __launch_bounds__((BM / TM) * (BN / TN))
void sgemm_kernel(const float* __restrict__ A, const float* __restrict__ B,
                  const float* __restrict__ bias, float* __restrict__ C,
                  int M, int N, int K, int doRelu) {
    constexpr int NT = (BM / TM) * (BN / TN);
    __shared__ float As[BK][BM];
    __shared__ float Bs[BK][BN];
    const int tid = threadIdx.x;
    const int tpr = BN / TN;
    const int tr = tid / tpr;
    const int tc = tid % tpr;
    const int rowBase = blockIdx.y * BM;
    const int colBase = blockIdx.x * BN;

    float acc[TM][TN];
#pragma unroll
    for (int i = 0; i < TM; i++)
#pragma unroll
        for (int j = 0; j < TN; j++) acc[i][j] = 0.0f;

    for (int k0 = 0; k0 < K; k0 += BK) {
        // A tile (guarded rows, float4, stored transposed)
        for (int i = tid; i < BM * BK / 4; i += NT) {
            int kq = i % (BK / 4);
            int m  = i / (BK / 4);
            float4 v = make_float4(0.f, 0.f, 0.f, 0.f);
            int gr = rowBase + m;
            if (gr < M) v = *(const float4*)&A[(size_t)gr * K + k0 + kq * 4];
            As[kq * 4 + 0][m] = v.x;
            As[kq * 4 + 1][m] = v.y;
            As[kq * 4 + 2][m] = v.z;
            As[kq * 4 + 3][m] = v.w;
        }
        // B tile
        for (int i = tid; i < BK * BN / 4; i += NT) {
            int nq = i % (BN / 4);
            int kk = i / (BN / 4);
            *(float4*)&Bs[kk][nq * 4] =
                *(const float4*)&B[(size_t)(k0 + kk) * N + colBase + nq * 4];
        }
        __syncthreads();
#pragma unroll
        for (int kk = 0; kk < BK; kk++) {
            float ra[TM], rb[TN];
#pragma unroll
            for (int i = 0; i < TM; i++) ra[i] = As[kk][tr * TM + i];
#pragma unroll
            for (int j = 0; j < TN; j++) rb[j] = Bs[kk][tc * TN + j];
#pragma unroll
            for (int i = 0; i < TM; i++)
#pragma unroll
                for (int j = 0; j < TN; j++) acc[i][j] += ra[i] * rb[j];
        }
        __syncthreads();
    }
#pragma unroll
    for (int i = 0; i < TM; i++) {
        int gr = rowBase + tr * TM + i;
        if (gr >= M) continue;
#pragma unroll
        for (int j = 0; j < TN; j++) {
            int gc = colBase + tc * TN + j;
            float val = acc[i][j] + (bias ? bias[gc] : 0.0f);
            if (doRelu) val = fmaxf(val, 0.0f);
            C[(size_t)gr * N + gc] = val;
        }
    }
}

// ---------------- layer-1 aggregation ----------------
__global__ void init_agg1_kernel(const float* __restrict__ b1) {
    int i = blockIdx.x * blockDim.x + threadIdx.x;     // float4 index
    if (i >= NN * (HH / 4)) return;
    int n = i / (HH / 4);
    int q = i % (HH / 4);
    float di = g_dinv[n];
    float sc = di * di;
    float4 xv = ((const float4*)g_xw1)[i];
    float4 bv = __ldg(&((const float4*)b1)[q]);
    float4 o;
    o.x = sc * xv.x + bv.x; o.y = sc * xv.y + bv.y;
    o.z = sc * xv.z + bv.z; o.w = sc * xv.w + bv.w;
    ((float4*)g_agg1)[i] = o;
}

__global__ void scatter1_kernel(const int* __restrict__ src, const int* __restrict__ dst) {
    const int EPW = 4;  // edges per warp
    int w = (blockIdx.x * blockDim.x + threadIdx.x) >> 5;
    int lane = threadIdx.x & 31;
    int e0 = w * EPW;
    int e1 = e0 + EPW; if (e1 > EE) e1 = EE;
    for (int e = e0; e < e1; e++) {
        int s = __ldg(&src[e]);
        int d = __ldg(&dst[e]);
        float nm = g_norm[e];
        float4 v = *(const float4*)&g_xw1[(size_t)s * HH + lane * 4];
        float* p = &g_agg1[(size_t)d * HH + lane * 4];
        asm volatile("red.global.add.v4.f32 [%0], {%1,%2,%3,%4};"
                     :: "l"(p), "f"(nm * v.x), "f"(nm * v.y), "f"(nm * v.z), "f"(nm * v.w)
                     : "memory");
    }
}

__global__ void relu1_kernel() {
    int i = blockIdx.x * blockDim.x + threadIdx.x;
    if (i >= NN * (HH / 4)) return;
    float4 v = ((const float4*)g_agg1)[i];
    v.x = fmaxf(v.x, 0.f); v.y = fmaxf(v.y, 0.f);
    v.z = fmaxf(v.z, 0.f); v.w = fmaxf(v.w, 0.f);
    ((float4*)g_agg1)[i] = v;
}

// ---------------- layer-2 aggregation ----------------
__global__ void init_agg2_kernel(const float* __restrict__ b2) {
    int i = blockIdx.x * blockDim.x + threadIdx.x;     // float4 index
    if (i >= NN * (CC / 4)) return;
    int n = i / (CC / 4);
    int q = i % (CC / 4);
    float di = g_dinv[n];
    float sc = di * di;
    float4 xv = ((const float4*)g_xw2)[i];
    float4 bv = __ldg(&((const float4*)b2)[q]);
    float4 o;
    o.x = sc * xv.x + bv.x; o.y = sc * xv.y + bv.y;
    o.z = sc * xv.z + bv.z; o.w = sc * xv.w + bv.w;
    ((float4*)g_agg2)[i] = o;
}

__global__ void scatter2_kernel(const int* __restrict__ src, const int* __restrict__ dst) {
    int gt = blockIdx.x * blockDim.x + threadIdx.x;
    int e = gt >> 2;          // 4 threads per edge (16 floats)
    int q = gt & 3;
    if (e >= EE) return;
    int s = __ldg(&src[e]);
    int d = __ldg(&dst[e]);
    float nm = g_norm[e];
    float4 v = ((const float4*)&g_xw2[(size_t)s * CC])[q];
    float* p = &g_agg2[(size_t)d * CC + q * 4];
    asm volatile("red.global.add.v4.f32 [%0], {%1,%2,%3,%4};"
                 :: "l"(p), "f"(nm * v.x), "f"(nm * v.y), "f"(nm * v.z), "f"(nm * v.w)
                 : "memory");
}

// ---------------- per-node: log_softmax, y_prob, u/v scalars ----------------
__global__ void node_kernel(const int* __restrict__ y, const void* __restrict__ tmask,
                            const float* __restrict__ Wd, float* __restrict__ out_lsm) {
    int n = blockIdx.x * blockDim.x + threadIdx.x;
    if (n >= NN) return;
    float l[CC];
    const float* lr = &g_agg2[(size_t)n * CC];
    float m = -1e30f;
#pragma unroll
    for (int c = 0; c < CC; c++) { l[c] = lr[c]; m = fmaxf(m, l[c]); }
    float se = 0.0f;
#pragma unroll
    for (int c = 0; c < CC; c++) se += expf(l[c] - m);
    float lse = logf(se);

    int kind = g_maskkind;
    bool msk;
    if (kind == 0)      msk = ((const int*)tmask)[n] != 0;
    else if (kind == 1) msk = ((const float*)tmask)[n] != 0.0f;
    else                msk = ((const unsigned char*)tmask)[n] != 0;
    int yc = y[n];

    float u = 0.0f, v = 0.0f;
#pragma unroll
    for (int c = 0; c < CC; c++) {
        float lsm = l[c] - m - lse;
        out_lsm[(size_t)n * CC + c] = lsm;
        float yp = msk ? ((c == yc) ? 1.0f : 0.0f) : expf(lsm);
        u += yp * __ldg(&Wd[128 + c]);
        v += yp * __ldg(&Wd[144 + c]);
    }
    const float4* xr = (const float4*)&g_xe[(size_t)n * HXD];
#pragma unroll
    for (int k4 = 0; k4 < HXD / 4; k4++) {
        float4 xv = xr[k4];
        int k = k4 * 4;
        u += xv.x * __ldg(&Wd[k + 0]) + xv.y * __ldg(&Wd[k + 1])
           + xv.z * __ldg(&Wd[k + 2]) + xv.w * __ldg(&Wd[k + 3]);
        v += xv.x * __ldg(&Wd[64 + k + 0]) + xv.y * __ldg(&Wd[64 + k + 1])
           + xv.z * __ldg(&Wd[64 + k + 2]) + xv.w * __ldg(&Wd[64 + k + 3]);
    }
    g_u[n] = u;
    g_v[n] = v;
}

// ---------------- edge decode ----------------
__global__ void decode_kernel(const int* __restrict__ pos, const int* __restrict__ neg,
                              const float* __restrict__ bd, float* __restrict__ out) {
    int i = blockIdx.x * blockDim.x + threadIdx.x;
    if (i >= 2 * EE) return;
    const int* ei = (i < EE) ? pos : neg;
    int k = (i < EE) ? i : i - EE;
    int s = ei[k];
    int d = ei[EE + k];
    out[i] = g_u[s] + g_v[d] + __ldg(bd);
}

// ---------------- launch ----------------
extern "C" void kernel_launch(void* const* d_in, const int* in_sizes, int n_in,
                              void* d_out, int out_size) {
    const float* x  = (const float*)d_in[0];
    const int* ei   = (const int*)d_in[1];   // [2, E] row-major: src then dst
    const int* nei  = (const int*)d_in[2];
    const int* y    = (const int*)d_in[3];
    const void* tm  = d_in[4];
    const float* W1 = (const float*)d_in[5];
    const float* b1 = (const float*)d_in[6];
    const float* W2 = (const float*)d_in[7];
    const float* b2 = (const float*)d_in[8];
    const float* Wx = (const float*)d_in[9];
    const float* bx = (const float*)d_in[10];
    const float* Wd = (const float*)d_in[11];
    const float* bd = (const float*)d_in[12];
    float* out = (float*)d_out;

    float *p_xw1, *p_xe, *p_agg1, *p_xw2;
    cudaGetSymbolAddress((void**)&p_xw1, g_xw1);
    cudaGetSymbolAddress((void**)&p_xe, g_xe);
    cudaGetSymbolAddress((void**)&p_agg1, g_agg1);
    cudaGetSymbolAddress((void**)&p_xw2, g_xw2);

    const int T = 256;

    detect_mask_kernel<<<1, 256>>>((const unsigned*)tm);
    deg_init_kernel<<<(NN + T - 1) / T, T>>>();
    deg_count_kernel<<<(EE + T - 1) / T, T>>>(ei + EE);
    dinv_kernel<<<(NN + T - 1) / T, T>>>();
    norm_kernel<<<(EE + T - 1) / T, T>>>(ei, ei + EE);

    {   // xw1 = x @ W1 (bias deferred to init_agg1)
        dim3 grid(HH / 128, (NN + 127) / 128);
        sgemm_kernel<128, 128, 16, 8, 8><<<grid, 256>>>(x, W1, nullptr, p_xw1, NN, HH, FF, 0);
    }
    {   // xe = relu(x @ Wx + bx)
        dim3 grid(HXD / 64, (NN + 127) / 128);
        sgemm_kernel<128, 64, 16, 8, 4><<<grid, 256>>>(x, Wx, bx, p_xe, NN, HXD, FF, 1);
    }

    init_agg1_kernel<<<(NN * (HH / 4) + T - 1) / T, T>>>(b1);
    {   // layer-1 scatter: one warp per edge, 4 edges/warp
        int warps = (EE + 3) / 4;
        int blocks = (warps * 32 + T - 1) / T;
        scatter1_kernel<<<blocks, T>>>(ei, ei + EE);
    }
    relu1_kernel<<<(NN * (HH / 4) + T - 1) / T, T>>>();

    {   // xw2 = h @ W2
        dim3 grid(CC / 16, (NN + 127) / 128);
        sgemm_kernel<128, 16, 16, 8, 2><<<grid, 128>>>(p_agg1, W2, nullptr, p_xw2, NN, CC, HH, 0);
    }
    init_agg2_kernel<<<(NN * (CC / 4) + T - 1) / T, T>>>(b2);
    scatter2_kernel<<<(EE * 4 + T - 1) / T, T>>>(ei, ei + EE);

    node_kernel<<<(NN + T - 1) / T, T>>>(y, tm, Wd, out + 2 * (size_t)EE);
    decode_kernel<<<(2 * EE + T - 1) / T, T>>>(ei, nei, bd, out);
}

// round 3
// speedup vs baseline: 1.0793x; 1.0793x over previous
#include <cuda_runtime.h>
#include <math.h>
#include <stdint.h>

#define NN  50000
#define FF  256
#define HH  128
#define CC  16
#define HXD 64
#define EE  500000

// ---------------- scratch (device globals; no allocation allowed) ----------------
__device__ float g_xw1 [(size_t)NN * HH];   // x @ W1
__device__ float g_xe  [(size_t)NN * HXD];  // relu(x @ Wx + bx)
__device__ float g_agg1[(size_t)NN * HH];   // layer-1 aggregate (relu fused into GEMM2 load)
__device__ float g_xw2 [(size_t)NN * CC];   // h @ W2
__device__ float g_agg2[(size_t)NN * CC];   // layer-2 aggregate = logits
__device__ float g_deg [NN];
__device__ float g_norm[EE];
__device__ float g_u   [NN];
__device__ float g_v   [NN];
__device__ int   g_maskkind;                // 0=int32, 1=float32, 2=byte/bool

// ---------------- prep: deg=1 (self loop) + train_mask dtype detection ----------------
__global__ void prep_kernel(const unsigned* __restrict__ tm) {
    int i = blockIdx.x * blockDim.x + threadIdx.x;
    if (i < NN) g_deg[i] = 1.0f;
    if (blockIdx.x == 0) {
        __shared__ int bad_int, bad_float;
        if (threadIdx.x == 0) { bad_int = 0; bad_float = 0; }
        __syncthreads();
        for (int j = threadIdx.x; j < 2048; j += blockDim.x) {
            unsigned v = tm[j];
            if (v > 1u) bad_int = 1;                          // benign write race
            if (v != 0u && v != 0x3F800000u) bad_float = 1;
        }
        __syncthreads();
        if (threadIdx.x == 0)
            g_maskkind = (bad_int == 0) ? 0 : ((bad_float == 0) ? 1 : 2);
    }
}

__global__ void deg_count_kernel(const int* __restrict__ dst) {
    int e = blockIdx.x * blockDim.x + threadIdx.x;
    if (e < EE) atomicAdd(&g_deg[dst[e]], 1.0f);
}

__global__ void norm_kernel(const int* __restrict__ src, const int* __restrict__ dst) {
    int e = blockIdx.x * blockDim.x + threadIdx.x;
    if (e < EE) g_norm[e] = rsqrtf(g_deg[src[e]]) * rsqrtf(g_deg[dst[e]]);
}

// ---------------- double-buffered fp32 GEMM: C = A@B (+bias, relu on out / relu on A) ----------------
template <int BM, int BN, int BK, int TM, int TN, bool RELU_A>
__global__ __launch_bounds__((BM / TM) * (BN / TN))
void sgemm_kernel(const float* __restrict__ A, const float* __restrict__ B,
                  const float* __restrict__ bias, float* __restrict__ C,
                  int M, int N, int K, int doRelu) {
    constexpr int NT = (BM / TM) * (BN / TN);
    constexpr int AV = BM * BK / 4;               // float4s per A tile
    constexpr int BV = BK * BN / 4;
    constexpr int AR = (AV + NT - 1) / NT;
    constexpr int BR = (BV + NT - 1) / NT;
    __shared__ float As[2][BK][BM];
    __shared__ float Bs[2][BK][BN];
    const int tid = threadIdx.x;
    const int tpr = BN / TN;
    const int tr = tid / tpr;
    const int tc = tid % tpr;
    const int rowBase = blockIdx.y * BM;
    const int colBase = blockIdx.x * BN;

    float4 aReg[AR], bReg[BR];

    auto loadTile = [&](int k0) {
#pragma unroll
        for (int r = 0; r < AR; r++) {
            int i = tid + r * NT;
            if ((AV % NT) && i >= AV) continue;
            int kq = i % (BK / 4);
            int m = i / (BK / 4);
            int gr = rowBase + m;
            float4 v = make_float4(0.f, 0.f, 0.f, 0.f);
            if (gr < M) v = *(const float4*)&A[(size_t)gr * K + k0 + kq * 4];
            if (RELU_A) {
                v.x = fmaxf(v.x, 0.f); v.y = fmaxf(v.y, 0.f);
                v.z = fmaxf(v.z, 0.f); v.w = fmaxf(v.w, 0.f);
            }
            aReg[r] = v;
        }
#pragma unroll
        for (int r = 0; r < BR; r++) {
            int i = tid + r * NT;
            if ((BV % NT) && i >= BV) continue;
            int nq = i % (BN / 4);
            int kk = i / (BN / 4);
            bReg[r] = *(const float4*)&B[(size_t)(k0 + kk) * N + colBase + nq * 4];
        }
    };
    auto storeTile = [&](int buf) {
#pragma unroll
        for (int r = 0; r < AR; r++) {
            int i = tid + r * NT;
            if ((AV % NT) && i >= AV) continue;
            int kq = i % (BK / 4);
            int m = i / (BK / 4);
            As[buf][kq * 4 + 0][m] = aReg[r].x;
            As[buf][kq * 4 + 1][m] = aReg[r].y;
            As[buf][kq * 4 + 2][m] = aReg[r].z;
            As[buf][kq * 4 + 3][m] = aReg[r].w;
        }
#pragma unroll
        for (int r = 0; r < BR; r++) {
            int i = tid + r * NT;
            if ((BV % NT) && i >= BV) continue;
            int nq = i % (BN / 4);
            int kk = i / (BN / 4);
            *(float4*)&Bs[buf][kk][nq * 4] = bReg[r];
        }
    };

    float acc[TM][TN];
#pragma unroll
    for (int i = 0; i < TM; i++)
#pragma unroll
        for (int j = 0; j < TN; j++) acc[i][j] = 0.0f;

    const int nTiles = K / BK;
    loadTile(0);
    storeTile(0);
    __syncthreads();
    int buf = 0;
    for (int t = 0; t < nTiles; t++) {
        if (t + 1 < nTiles) loadTile((t + 1) * BK);
#pragma unroll
        for (int kk = 0; kk < BK; kk++) {
            float ra[TM], rb[TN];
#pragma unroll
            for (int i = 0; i < TM; i++) ra[i] = As[buf][kk][tr * TM + i];
#pragma unroll
            for (int j = 0; j < TN; j++) rb[j] = Bs[buf][kk][tc * TN + j];
#pragma unroll
            for (int i = 0; i < TM; i++)
#pragma unroll
                for (int j = 0; j < TN; j++) acc[i][j] += ra[i] * rb[j];
        }
        if (t + 1 < nTiles) storeTile(buf ^ 1);
        __syncthreads();
        buf ^= 1;
    }

#pragma unroll
    for (int i = 0; i < TM; i++) {
        int gr = rowBase + tr * TM + i;
        if (gr >= M) continue;
#pragma unroll
        for (int j = 0; j < TN; j++) {
            int gc = colBase + tc * TN + j;
            float val = acc[i][j] + (bias ? bias[gc] : 0.0f);
            if (doRelu) val = fmaxf(val, 0.0f);
            C[(size_t)gr * N + gc] = val;
        }
    }
}

// ---------------- layer-1 aggregation ----------------
__global__ void init_agg1_kernel(const float* __restrict__ b1) {
    int i = blockIdx.x * blockDim.x + threadIdx.x;     // float4 index
    if (i >= NN * (HH / 4)) return;
    int n = i / (HH / 4);
    int q = i % (HH / 4);
    float di = rsqrtf(g_deg[n]);
    float sc = di * di;
    float4 xv = ((const float4*)g_xw1)[i];
    float4 bv = __ldg(&((const float4*)b1)[q]);
    float4 o;
    o.x = sc * xv.x + bv.x; o.y = sc * xv.y + bv.y;
    o.z = sc * xv.z + bv.z; o.w = sc * xv.w + bv.w;
    ((float4*)g_agg1)[i] = o;
}

__global__ void scatter1_kernel(const int* __restrict__ src, const int* __restrict__ dst) {
    const int EPW = 4;  // edges per warp
    int w = (blockIdx.x * blockDim.x + threadIdx.x) >> 5;
    int lane = threadIdx.x & 31;
    int e0 = w * EPW;
    int e1 = e0 + EPW; if (e1 > EE) e1 = EE;
    for (int e = e0; e < e1; e++) {
        int s = __ldg(&src[e]);
        int d = __ldg(&dst[e]);
        float nm = g_norm[e];
        float4 v = *(const float4*)&g_xw1[(size_t)s * HH + lane * 4];
        float* p = &g_agg1[(size_t)d * HH + lane * 4];
        asm volatile("red.global.add.v4.f32 [%0], {%1,%2,%3,%4};"
                     :: "l"(p), "f"(nm * v.x), "f"(nm * v.y), "f"(nm * v.z), "f"(nm * v.w)
                     : "memory");
    }
}

// ---------------- layer-2 aggregation ----------------
__global__ void init_agg2_kernel(const float* __restrict__ b2) {
    int i = blockIdx.x * blockDim.x + threadIdx.x;     // float4 index
    if (i >= NN * (CC / 4)) return;
    int n = i / (CC / 4);
    int q = i % (CC / 4);
    float di = rsqrtf(g_deg[n]);
    float sc = di * di;
    float4 xv = ((const float4*)g_xw2)[i];
    float4 bv = __ldg(&((const float4*)b2)[q]);
    float4 o;
    o.x = sc * xv.x + bv.x; o.y = sc * xv.y + bv.y;
    o.z = sc * xv.z + bv.z; o.w = sc * xv.w + bv.w;
    ((float4*)g_agg2)[i] = o;
}

__global__ void scatter2_kernel(const int* __restrict__ src, const int* __restrict__ dst) {
    int gt = blockIdx.x * blockDim.x + threadIdx.x;
    int e = gt >> 2;          // 4 threads per edge (16 floats)
    int q = gt & 3;
    if (e >= EE) return;
    int s = __ldg(&src[e]);
    int d = __ldg(&dst[e]);
    float nm = g_norm[e];
    float4 v = ((const float4*)&g_xw2[(size_t)s * CC])[q];
    float* p = &g_agg2[(size_t)d * CC + q * 4];
    asm volatile("red.global.add.v4.f32 [%0], {%1,%2,%3,%4};"
                 :: "l"(p), "f"(nm * v.x), "f"(nm * v.y), "f"(nm * v.z), "f"(nm * v.w)
                 : "memory");
}

// ---------------- per-node: log_softmax, y_prob, u/v scalars ----------------
__global__ void node_kernel(const int* __restrict__ y, const void* __restrict__ tmask,
                            const float* __restrict__ Wd, float* __restrict__ out_lsm) {
    int n = blockIdx.x * blockDim.x + threadIdx.x;
    if (n >= NN) return;
    float l[CC];
    const float* lr = &g_agg2[(size_t)n * CC];
    float m = -1e30f;
#pragma unroll
    for (int c = 0; c < CC; c++) { l[c] = lr[c]; m = fmaxf(m, l[c]); }
    float se = 0.0f;
#pragma unroll
    for (int c = 0; c < CC; c++) se += expf(l[c] - m);
    float lse = logf(se);

    int kind = g_maskkind;
    bool msk;
    if (kind == 0)      msk = ((const int*)tmask)[n] != 0;
    else if (kind == 1) msk = ((const float*)tmask)[n] != 0.0f;
    else                msk = ((const unsigned char*)tmask)[n] != 0;
    int yc = y[n];

    float u = 0.0f, v = 0.0f;
#pragma unroll
    for (int c = 0; c < CC; c++) {
        float lsm = l[c] - m - lse;
        out_lsm[(size_t)n * CC + c] = lsm;
        float yp = msk ? ((c == yc) ? 1.0f : 0.0f) : expf(lsm);
        u += yp * __ldg(&Wd[128 + c]);
        v += yp * __ldg(&Wd[144 + c]);
    }
    const float4* xr = (const float4*)&g_xe[(size_t)n * HXD];
#pragma unroll
    for (int k4 = 0; k4 < HXD / 4; k4++) {
        float4 xv = xr[k4];
        int k = k4 * 4;
        u += xv.x * __ldg(&Wd[k + 0]) + xv.y * __ldg(&Wd[k + 1])
           + xv.z * __ldg(&Wd[k + 2]) + xv.w * __ldg(&Wd[k + 3]);
        v += xv.x * __ldg(&Wd[64 + k + 0]) + xv.y * __ldg(&Wd[64 + k + 1])
           + xv.z * __ldg(&Wd[64 + k + 2]) + xv.w * __ldg(&Wd[64 + k + 3]);
    }
    g_u[n] = u;
    g_v[n] = v;
}

// ---------------- edge decode ----------------
__global__ void decode_kernel(const int* __restrict__ pos, const int* __restrict__ neg,
                              const float* __restrict__ bd, float* __restrict__ out) {
    int i = blockIdx.x * blockDim.x + threadIdx.x;
    if (i >= 2 * EE) return;
    const int* ei = (i < EE) ? pos : neg;
    int k = (i < EE) ? i : i - EE;
    int s = ei[k];
    int d = ei[EE + k];
    out[i] = g_u[s] + g_v[d] + __ldg(bd);
}

// ---------------- launch ----------------
extern "C" void kernel_launch(void* const* d_in, const int* in_sizes, int n_in,
                              void* d_out, int out_size) {
    const float* x  = (const float*)d_in[0];
    const int* ei   = (const int*)d_in[1];   // [2, E] row-major: src then dst
    const int* nei  = (const int*)d_in[2];
    const int* y    = (const int*)d_in[3];
    const void* tm  = d_in[4];
    const float* W1 = (const float*)d_in[5];
    const float* b1 = (const float*)d_in[6];
    const float* W2 = (const float*)d_in[7];
    const float* b2 = (const float*)d_in[8];
    const float* Wx = (const float*)d_in[9];
    const float* bx = (const float*)d_in[10];
    const float* Wd = (const float*)d_in[11];
    const float* bd = (const float*)d_in[12];
    float* out = (float*)d_out;

    float *p_xw1, *p_xe, *p_agg1, *p_xw2;
    cudaGetSymbolAddress((void**)&p_xw1, g_xw1);
    cudaGetSymbolAddress((void**)&p_xe, g_xe);
    cudaGetSymbolAddress((void**)&p_agg1, g_agg1);
    cudaGetSymbolAddress((void**)&p_xw2, g_xw2);

    const int T = 256;

    prep_kernel<<<(NN + T - 1) / T, T>>>((const unsigned*)tm);
    deg_count_kernel<<<(EE + T - 1) / T, T>>>(ei + EE);
    norm_kernel<<<(EE + T - 1) / T, T>>>(ei, ei + EE);

    {   // xw1 = x @ W1 (bias deferred to init_agg1)
        dim3 grid(HH / 128, (NN + 127) / 128);
        sgemm_kernel<128, 128, 16, 8, 8, false><<<grid, 256>>>(x, W1, nullptr, p_xw1, NN, HH, FF, 0);
    }
    {   // xe = relu(x @ Wx + bx)
        dim3 grid(HXD / 64, (NN + 127) / 128);
        sgemm_kernel<128, 64, 16, 8, 4, false><<<grid, 256>>>(x, Wx, bx, p_xe, NN, HXD, FF, 1);
    }

    init_agg1_kernel<<<(NN * (HH / 4) + T - 1) / T, T>>>(b1);
    {   // layer-1 scatter: one warp per edge, 4 edges/warp
        int warps = (EE + 3) / 4;
        int blocks = (warps * 32 + T - 1) / T;
        scatter1_kernel<<<blocks, T>>>(ei, ei + EE);
    }

    {   // xw2 = relu(agg1) @ W2 — relu fused into A load
        dim3 grid(CC / 16, (NN + 127) / 128);
        sgemm_kernel<128, 16, 16, 8, 2, true><<<grid, 128>>>(p_agg1, W2, nullptr, p_xw2, NN, CC, HH, 0);
    }
    init_agg2_kernel<<<(NN * (CC / 4) + T - 1) / T, T>>>(b2);
    scatter2_kernel<<<(EE * 4 + T - 1) / T, T>>>(ei, ei + EE);

    node_kernel<<<(NN + T - 1) / T, T>>>(y, tm, Wd, out + 2 * (size_t)EE);
    decode_kernel<<<(2 * EE + T - 1) / T, T>>>(ei, nei, bd, out);
}

// round 4
// speedup vs baseline: 1.0830x; 1.0034x over previous
#include <cuda_runtime.h>
#include <math.h>
#include <stdint.h>

#define NN  50000
#define FF  256
#define HH  128
#define CC  16
#define HXD 64
#define EE  500000

// ---------------- scratch (device globals; no allocation allowed) ----------------
__device__ float g_xw1 [(size_t)NN * HH];   // x @ W1
__device__ float g_xe  [(size_t)NN * HXD];  // relu(x @ Wx + bx)
__device__ float g_agg1[(size_t)NN * HH];   // layer-1 aggregate (relu fused into GEMM2 load)
__device__ float g_xw2 [(size_t)NN * CC];   // h @ W2
__device__ float g_agg2[(size_t)NN * CC];   // layer-2 aggregate = logits
__device__ float g_deg [NN];
__device__ float g_norm[EE];
__device__ float g_u   [NN];
__device__ float g_v   [NN];
__device__ int   g_maskkind;                // 0=int32, 1=float32, 2=byte/bool

// ---------------- prep: deg=1 (self loop) + train_mask dtype detection ----------------
__global__ void prep_kernel(const unsigned* __restrict__ tm) {
    int i = blockIdx.x * blockDim.x + threadIdx.x;
    if (i < NN) g_deg[i] = 1.0f;
    if (blockIdx.x == 0) {
        __shared__ int bad_int, bad_float;
        if (threadIdx.x == 0) { bad_int = 0; bad_float = 0; }
        __syncthreads();
        for (int j = threadIdx.x; j < 2048; j += blockDim.x) {
            unsigned v = tm[j];
            if (v > 1u) bad_int = 1;                          // benign write race
            if (v != 0u && v != 0x3F800000u) bad_float = 1;
        }
        __syncthreads();
        if (threadIdx.x == 0)
            g_maskkind = (bad_int == 0) ? 0 : ((bad_float == 0) ? 1 : 2);
    }
}

__global__ void deg_count_kernel(const int* __restrict__ dst) {
    int e = blockIdx.x * blockDim.x + threadIdx.x;
    if (e < EE) atomicAdd(&g_deg[dst[e]], 1.0f);
}

__global__ void norm_kernel(const int* __restrict__ src, const int* __restrict__ dst) {
    int e = blockIdx.x * blockDim.x + threadIdx.x;
    if (e < EE) g_norm[e] = rsqrtf(g_deg[src[e]]) * rsqrtf(g_deg[dst[e]]);
}

// ---------------- double-buffered fp32 GEMM (smem + register fragment pipeline) ----------------
template <int BM, int BN, int BK, int TM, int TN, bool RELU_A, int MINB>
__global__ __launch_bounds__((BM / TM) * (BN / TN), MINB)
void sgemm_kernel(const float* __restrict__ A, const float* __restrict__ B,
                  const float* __restrict__ bias, float* __restrict__ C,
                  int M, int N, int K, int doRelu) {
    constexpr int NT = (BM / TM) * (BN / TN);
    constexpr int AV = BM * BK / 4;               // float4s per A tile
    constexpr int BV = BK * BN / 4;
    constexpr int AR = (AV + NT - 1) / NT;
    constexpr int BR = (BV + NT - 1) / NT;
    __shared__ float As[2][BK][BM];
    __shared__ float Bs[2][BK][BN];
    const int tid = threadIdx.x;
    const int tpr = BN / TN;
    const int tr = tid / tpr;
    const int tc = tid % tpr;
    const int rowBase = blockIdx.y * BM;
    const int colBase = blockIdx.x * BN;

    float4 aReg[AR], bReg[BR];

    auto loadTile = [&](int k0) {
#pragma unroll
        for (int r = 0; r < AR; r++) {
            int i = tid + r * NT;
            if ((AV % NT) && i >= AV) continue;
            int kq = i % (BK / 4);
            int m = i / (BK / 4);
            int gr = rowBase + m;
            float4 v = make_float4(0.f, 0.f, 0.f, 0.f);
            if (gr < M) v = *(const float4*)&A[(size_t)gr * K + k0 + kq * 4];
            if (RELU_A) {
                v.x = fmaxf(v.x, 0.f); v.y = fmaxf(v.y, 0.f);
                v.z = fmaxf(v.z, 0.f); v.w = fmaxf(v.w, 0.f);
            }
            aReg[r] = v;
        }
#pragma unroll
        for (int r = 0; r < BR; r++) {
            int i = tid + r * NT;
            if ((BV % NT) && i >= BV) continue;
            int nq = i % (BN / 4);
            int kk = i / (BN / 4);
            bReg[r] = *(const float4*)&B[(size_t)(k0 + kk) * N + colBase + nq * 4];
        }
    };
    auto storeTile = [&](int buf) {
#pragma unroll
        for (int r = 0; r < AR; r++) {
            int i = tid + r * NT;
            if ((AV % NT) && i >= AV) continue;
            int kq = i % (BK / 4);
            int m = i / (BK / 4);
            As[buf][kq * 4 + 0][m] = aReg[r].x;
            As[buf][kq * 4 + 1][m] = aReg[r].y;
            As[buf][kq * 4 + 2][m] = aReg[r].z;
            As[buf][kq * 4 + 3][m] = aReg[r].w;
        }
#pragma unroll
        for (int r = 0; r < BR; r++) {
            int i = tid + r * NT;
            if ((BV % NT) && i >= BV) continue;
            int nq = i % (BN / 4);
            int kk = i / (BN / 4);
            *(float4*)&Bs[buf][kk][nq * 4] = bReg[r];
        }
    };

    float acc[TM][TN];
#pragma unroll
    for (int i = 0; i < TM; i++)
#pragma unroll
        for (int j = 0; j < TN; j++) acc[i][j] = 0.0f;

    // register fragment double buffer
    float ra[2][TM], rb[2][TN];

    const int nTiles = K / BK;
    loadTile(0);
    storeTile(0);
    __syncthreads();
    int buf = 0;
    for (int t = 0; t < nTiles; t++) {
        if (t + 1 < nTiles) loadTile((t + 1) * BK);
        // preload fragment kk=0
#pragma unroll
        for (int i = 0; i < TM; i++) ra[0][i] = As[buf][0][tr * TM + i];
#pragma unroll
        for (int j = 0; j < TN; j++) rb[0][j] = Bs[buf][0][tc * TN + j];
#pragma unroll
        for (int kk = 0; kk < BK; kk++) {
            int cur = kk & 1, nxt = cur ^ 1;
            if (kk + 1 < BK) {
#pragma unroll
                for (int i = 0; i < TM; i++) ra[nxt][i] = As[buf][kk + 1][tr * TM + i];
#pragma unroll
                for (int j = 0; j < TN; j++) rb[nxt][j] = Bs[buf][kk + 1][tc * TN + j];
            }
#pragma unroll
            for (int i = 0; i < TM; i++)
#pragma unroll
                for (int j = 0; j < TN; j++) acc[i][j] += ra[cur][i] * rb[cur][j];
        }
        if (t + 1 < nTiles) storeTile(buf ^ 1);
        __syncthreads();
        buf ^= 1;
    }

#pragma unroll
    for (int i = 0; i < TM; i++) {
        int gr = rowBase + tr * TM + i;
        if (gr >= M) continue;
#pragma unroll
        for (int j = 0; j < TN; j++) {
            int gc = colBase + tc * TN + j;
            float val = acc[i][j] + (bias ? bias[gc] : 0.0f);
            if (doRelu) val = fmaxf(val, 0.0f);
            C[(size_t)gr * N + gc] = val;
        }
    }
}

// ---------------- layer-1 aggregation ----------------
__global__ void init_agg1_kernel(const float* __restrict__ b1) {
    int i = blockIdx.x * blockDim.x + threadIdx.x;     // float4 index
    if (i >= NN * (HH / 4)) return;
    int n = i / (HH / 4);
    int q = i % (HH / 4);
    float di = rsqrtf(g_deg[n]);
    float sc = di * di;
    float4 xv = ((const float4*)g_xw1)[i];
    float4 bv = __ldg(&((const float4*)b1)[q]);
    float4 o;
    o.x = sc * xv.x + bv.x; o.y = sc * xv.y + bv.y;
    o.z = sc * xv.z + bv.z; o.w = sc * xv.w + bv.w;
    ((float4*)g_agg1)[i] = o;
}

__global__ void scatter1_kernel(const int* __restrict__ src, const int* __restrict__ dst) {
    const int EPW = 4;  // edges per warp
    int w = (blockIdx.x * blockDim.x + threadIdx.x) >> 5;
    int lane = threadIdx.x & 31;
    int e0 = w * EPW;
    int e1 = e0 + EPW; if (e1 > EE) e1 = EE;
    for (int e = e0; e < e1; e++) {
        int s = __ldg(&src[e]);
        int d = __ldg(&dst[e]);
        float nm = g_norm[e];
        float4 v = *(const float4*)&g_xw1[(size_t)s * HH + lane * 4];
        float* p = &g_agg1[(size_t)d * HH + lane * 4];
        asm volatile("red.global.add.v4.f32 [%0], {%1,%2,%3,%4};"
                     :: "l"(p), "f"(nm * v.x), "f"(nm * v.y), "f"(nm * v.z), "f"(nm * v.w)
                     : "memory");
    }
}

// ---------------- layer-2 aggregation ----------------
__global__ void init_agg2_kernel(const float* __restrict__ b2) {
    int i = blockIdx.x * blockDim.x + threadIdx.x;     // float4 index
    if (i >= NN * (CC / 4)) return;
    int n = i / (CC / 4);
    int q = i % (CC / 4);
    float di = rsqrtf(g_deg[n]);
    float sc = di * di;
    float4 xv = ((const float4*)g_xw2)[i];
    float4 bv = __ldg(&((const float4*)b2)[q]);
    float4 o;
    o.x = sc * xv.x + bv.x; o.y = sc * xv.y + bv.y;
    o.z = sc * xv.z + bv.z; o.w = sc * xv.w + bv.w;
    ((float4*)g_agg2)[i] = o;
}

__global__ void scatter2_kernel(const int* __restrict__ src, const int* __restrict__ dst) {
    int gt = blockIdx.x * blockDim.x + threadIdx.x;
    int e = gt >> 2;          // 4 threads per edge (16 floats)
    int q = gt & 3;
    if (e >= EE) return;
    int s = __ldg(&src[e]);
    int d = __ldg(&dst[e]);
    float nm = g_norm[e];
    float4 v = ((const float4*)&g_xw2[(size_t)s * CC])[q];
    float* p = &g_agg2[(size_t)d * CC + q * 4];
    asm volatile("red.global.add.v4.f32 [%0], {%1,%2,%3,%4};"
                 :: "l"(p), "f"(nm * v.x), "f"(nm * v.y), "f"(nm * v.z), "f"(nm * v.w)
                 : "memory");
}

// ---------------- per-node: log_softmax, y_prob, u/v scalars ----------------
__global__ void node_kernel(const int* __restrict__ y, const void* __restrict__ tmask,
                            const float* __restrict__ Wd, float* __restrict__ out_lsm) {
    int n = blockIdx.x * blockDim.x + threadIdx.x;
    if (n >= NN) return;
    float l[CC];
    const float* lr = &g_agg2[(size_t)n * CC];
    float m = -1e30f;
#pragma unroll
    for (int c = 0; c < CC; c++) { l[c] = lr[c]; m = fmaxf(m, l[c]); }
    float se = 0.0f;
#pragma unroll
    for (int c = 0; c < CC; c++) se += expf(l[c] - m);
    float lse = logf(se);

    int kind = g_maskkind;
    bool msk;
    if (kind == 0)      msk = ((const int*)tmask)[n] != 0;
    else if (kind == 1) msk = ((const float*)tmask)[n] != 0.0f;
    else                msk = ((const unsigned char*)tmask)[n] != 0;
    int yc = y[n];

    float u = 0.0f, v = 0.0f;
#pragma unroll
    for (int c = 0; c < CC; c++) {
        float lsm = l[c] - m - lse;
        out_lsm[(size_t)n * CC + c] = lsm;
        float yp = msk ? ((c == yc) ? 1.0f : 0.0f) : expf(lsm);
        u += yp * __ldg(&Wd[128 + c]);
        v += yp * __ldg(&Wd[144 + c]);
    }
    const float4* xr = (const float4*)&g_xe[(size_t)n * HXD];
#pragma unroll
    for (int k4 = 0; k4 < HXD / 4; k4++) {
        float4 xv = xr[k4];
        int k = k4 * 4;
        u += xv.x * __ldg(&Wd[k + 0]) + xv.y * __ldg(&Wd[k + 1])
           + xv.z * __ldg(&Wd[k + 2]) + xv.w * __ldg(&Wd[k + 3]);
        v += xv.x * __ldg(&Wd[64 + k + 0]) + xv.y * __ldg(&Wd[64 + k + 1])
           + xv.z * __ldg(&Wd[64 + k + 2]) + xv.w * __ldg(&Wd[64 + k + 3]);
    }
    g_u[n] = u;
    g_v[n] = v;
}

// ---------------- edge decode ----------------
__global__ void decode_kernel(const int* __restrict__ pos, const int* __restrict__ neg,
                              const float* __restrict__ bd, float* __restrict__ out) {
    int i = blockIdx.x * blockDim.x + threadIdx.x;
    if (i >= 2 * EE) return;
    const int* ei = (i < EE) ? pos : neg;
    int k = (i < EE) ? i : i - EE;
    int s = ei[k];
    int d = ei[EE + k];
    out[i] = g_u[s] + g_v[d] + __ldg(bd);
}

// ---------------- launch ----------------
extern "C" void kernel_launch(void* const* d_in, const int* in_sizes, int n_in,
                              void* d_out, int out_size) {
    const float* x  = (const float*)d_in[0];
    const int* ei   = (const int*)d_in[1];   // [2, E] row-major: src then dst
    const int* nei  = (const int*)d_in[2];
    const int* y    = (const int*)d_in[3];
    const void* tm  = d_in[4];
    const float* W1 = (const float*)d_in[5];
    const float* b1 = (const float*)d_in[6];
    const float* W2 = (const float*)d_in[7];
    const float* b2 = (const float*)d_in[8];
    const float* Wx = (const float*)d_in[9];
    const float* bx = (const float*)d_in[10];
    const float* Wd = (const float*)d_in[11];
    const float* bd = (const float*)d_in[12];
    float* out = (float*)d_out;

    float *p_xw1, *p_xe, *p_agg1, *p_xw2;
    cudaGetSymbolAddress((void**)&p_xw1, g_xw1);
    cudaGetSymbolAddress((void**)&p_xe, g_xe);
    cudaGetSymbolAddress((void**)&p_agg1, g_agg1);
    cudaGetSymbolAddress((void**)&p_xw2, g_xw2);

    const int T = 256;

    prep_kernel<<<(NN + T - 1) / T, T>>>((const unsigned*)tm);
    deg_count_kernel<<<(EE + T - 1) / T, T>>>(ei + EE);
    norm_kernel<<<(EE + T - 1) / T, T>>>(ei, ei + EE);

    {   // xw1 = x @ W1 (bias deferred to init_agg1); 2 CTAs/SM forced
        dim3 grid(HH / 128, (NN + 127) / 128);
        sgemm_kernel<128, 128, 16, 8, 8, false, 2><<<grid, 256>>>(x, W1, nullptr, p_xw1, NN, HH, FF, 0);
    }
    {   // xe = relu(x @ Wx + bx)
        dim3 grid(HXD / 64, (NN + 127) / 128);
        sgemm_kernel<128, 64, 16, 8, 4, false, 2><<<grid, 256>>>(x, Wx, bx, p_xe, NN, HXD, FF, 1);
    }

    init_agg1_kernel<<<(NN * (HH / 4) + T - 1) / T, T>>>(b1);
    {   // layer-1 scatter: one warp per edge, 4 edges/warp
        int warps = (EE + 3) / 4;
        int blocks = (warps * 32 + T - 1) / T;
        scatter1_kernel<<<blocks, T>>>(ei, ei + EE);
    }

    {   // xw2 = relu(agg1) @ W2 — relu fused into A load
        dim3 grid(CC / 16, (NN + 127) / 128);
        sgemm_kernel<128, 16, 16, 8, 2, true, 2><<<grid, 128>>>(p_agg1, W2, nullptr, p_xw2, NN, CC, HH, 0);
    }
    init_agg2_kernel<<<(NN * (CC / 4) + T - 1) / T, T>>>(b2);
    scatter2_kernel<<<(EE * 4 + T - 1) / T, T>>>(ei, ei + EE);

    node_kernel<<<(NN + T - 1) / T, T>>>(y, tm, Wd, out + 2 * (size_t)EE);
    decode_kernel<<<(2 * EE + T - 1) / T, T>>>(ei, nei, bd, out);
}

// round 5
// speedup vs baseline: 1.2064x; 1.1139x over previous
#include <cuda_runtime.h>
#include <math.h>
#include <stdint.h>

#define NN  50000
#define FF  256
#define HH  128
#define CC  16
#define HXD 64
#define EE  500000

// ---------------- scratch (device globals; no allocation allowed) ----------------
__device__ float g_xw1 [(size_t)NN * HH];   // x @ W1
__device__ float g_xe  [(size_t)NN * HXD];  // relu(x @ Wx + bx)
__device__ float g_agg1[(size_t)NN * HH];   // layer-1 aggregate (relu fused into GEMM2 load)
__device__ float g_xw2 [(size_t)NN * CC];   // h @ W2
__device__ float g_agg2[(size_t)NN * CC];   // layer-2 aggregate = logits
__device__ float g_deg [NN];
__device__ float g_norm[EE];
__device__ float g_u   [NN];
__device__ float g_v   [NN];
__device__ int   g_maskkind;                // 0=int32, 1=float32, 2=byte/bool

// ---------------- prep: deg=1 (self loop) + train_mask dtype detection ----------------
__global__ void prep_kernel(const unsigned* __restrict__ tm) {
    int i = blockIdx.x * blockDim.x + threadIdx.x;
    if (i < NN) g_deg[i] = 1.0f;
    if (blockIdx.x == 0) {
        __shared__ int bad_int, bad_float;
        if (threadIdx.x == 0) { bad_int = 0; bad_float = 0; }
        __syncthreads();
        for (int j = threadIdx.x; j < 2048; j += blockDim.x) {
            unsigned v = tm[j];
            if (v > 1u) bad_int = 1;                          // benign write race
            if (v != 0u && v != 0x3F800000u) bad_float = 1;
        }
        __syncthreads();
        if (threadIdx.x == 0)
            g_maskkind = (bad_int == 0) ? 0 : ((bad_float == 0) ? 1 : 2);
    }
}

__global__ void deg_count_kernel(const int* __restrict__ dst) {
    int e = blockIdx.x * blockDim.x + threadIdx.x;
    if (e < EE) atomicAdd(&g_deg[dst[e]], 1.0f);
}

__global__ void norm_kernel(const int* __restrict__ src, const int* __restrict__ dst) {
    int e = blockIdx.x * blockDim.x + threadIdx.x;
    if (e < EE) g_norm[e] = rsqrtf(g_deg[src[e]]) * rsqrtf(g_deg[dst[e]]);
}

// ---------------- double-buffered (smem only) fp32 GEMM ----------------
template <int BM, int BN, int BK, int TM, int TN, bool RELU_A, int MINB>
__global__ __launch_bounds__((BM / TM) * (BN / TN), MINB)
void sgemm_kernel(const float* __restrict__ A, const float* __restrict__ B,
                  const float* __restrict__ bias, float* __restrict__ C,
                  int M, int N, int K, int doRelu) {
    constexpr int NT = (BM / TM) * (BN / TN);
    constexpr int AV = BM * BK / 4;               // float4s per A tile
    constexpr int BV = BK * BN / 4;
    constexpr int AR = (AV + NT - 1) / NT;
    constexpr int BR = (BV + NT - 1) / NT;
    __shared__ float As[2][BK][BM];
    __shared__ float Bs[2][BK][BN];
    const int tid = threadIdx.x;
    const int tpr = BN / TN;
    const int tr = tid / tpr;
    const int tc = tid % tpr;
    const int rowBase = blockIdx.y * BM;
    const int colBase = blockIdx.x * BN;

    float4 aReg[AR], bReg[BR];

    auto loadTile = [&](int k0) {
#pragma unroll
        for (int r = 0; r < AR; r++) {
            int i = tid + r * NT;
            if ((AV % NT) && i >= AV) continue;
            int kq = i % (BK / 4);
            int m = i / (BK / 4);
            int gr = rowBase + m;
            float4 v = make_float4(0.f, 0.f, 0.f, 0.f);
            if (gr < M) v = *(const float4*)&A[(size_t)gr * K + k0 + kq * 4];
            if (RELU_A) {
                v.x = fmaxf(v.x, 0.f); v.y = fmaxf(v.y, 0.f);
                v.z = fmaxf(v.z, 0.f); v.w = fmaxf(v.w, 0.f);
            }
            aReg[r] = v;
        }
#pragma unroll
        for (int r = 0; r < BR; r++) {
            int i = tid + r * NT;
            if ((BV % NT) && i >= BV) continue;
            int nq = i % (BN / 4);
            int kk = i / (BN / 4);
            bReg[r] = *(const float4*)&B[(size_t)(k0 + kk) * N + colBase + nq * 4];
        }
    };
    auto storeTile = [&](int buf) {
#pragma unroll
        for (int r = 0; r < AR; r++) {
            int i = tid + r * NT;
            if ((AV % NT) && i >= AV) continue;
            int kq = i % (BK / 4);
            int m = i / (BK / 4);
            As[buf][kq * 4 + 0][m] = aReg[r].x;
            As[buf][kq * 4 + 1][m] = aReg[r].y;
            As[buf][kq * 4 + 2][m] = aReg[r].z;
            As[buf][kq * 4 + 3][m] = aReg[r].w;
        }
#pragma unroll
        for (int r = 0; r < BR; r++) {
            int i = tid + r * NT;
            if ((BV % NT) && i >= BV) continue;
            int nq = i % (BN / 4);
            int kk = i / (BN / 4);
            *(float4*)&Bs[buf][kk][nq * 4] = bReg[r];
        }
    };

    float acc[TM][TN];
#pragma unroll
    for (int i = 0; i < TM; i++)
#pragma unroll
        for (int j = 0; j < TN; j++) acc[i][j] = 0.0f;

    const int nTiles = K / BK;
    loadTile(0);
    storeTile(0);
    __syncthreads();
    int buf = 0;
    for (int t = 0; t < nTiles; t++) {
        if (t + 1 < nTiles) loadTile((t + 1) * BK);
#pragma unroll
        for (int kk = 0; kk < BK; kk++) {
            float ra[TM], rb[TN];
#pragma unroll
            for (int i = 0; i < TM; i++) ra[i] = As[buf][kk][tr * TM + i];
#pragma unroll
            for (int j = 0; j < TN; j++) rb[j] = Bs[buf][kk][tc * TN + j];
#pragma unroll
            for (int i = 0; i < TM; i++)
#pragma unroll
                for (int j = 0; j < TN; j++) acc[i][j] += ra[i] * rb[j];
        }
        if (t + 1 < nTiles) storeTile(buf ^ 1);
        __syncthreads();
        buf ^= 1;
    }

#pragma unroll
    for (int i = 0; i < TM; i++) {
        int gr = rowBase + tr * TM + i;
        if (gr >= M) continue;
#pragma unroll
        for (int j = 0; j < TN; j++) {
            int gc = colBase + tc * TN + j;
            float val = acc[i][j] + (bias ? bias[gc] : 0.0f);
            if (doRelu) val = fmaxf(val, 0.0f);
            C[(size_t)gr * N + gc] = val;
        }
    }
}

// ---------------- layer-1 aggregation ----------------
__global__ void init_agg1_kernel(const float* __restrict__ b1) {
    int i = blockIdx.x * blockDim.x + threadIdx.x;     // float4 index
    if (i >= NN * (HH / 4)) return;
    int n = i / (HH / 4);
    int q = i % (HH / 4);
    float di = rsqrtf(g_deg[n]);
    float sc = di * di;
    float4 xv = ((const float4*)g_xw1)[i];
    float4 bv = __ldg(&((const float4*)b1)[q]);
    float4 o;
    o.x = sc * xv.x + bv.x; o.y = sc * xv.y + bv.y;
    o.z = sc * xv.z + bv.z; o.w = sc * xv.w + bv.w;
    ((float4*)g_agg1)[i] = o;
}

__global__ void scatter1_kernel(const int* __restrict__ src, const int* __restrict__ dst) {
    const int EPW = 4;  // edges per warp
    int w = (blockIdx.x * blockDim.x + threadIdx.x) >> 5;
    int lane = threadIdx.x & 31;
    int e0 = w * EPW;
    int e1 = e0 + EPW; if (e1 > EE) e1 = EE;
    for (int e = e0; e < e1; e++) {
        int s = __ldg(&src[e]);
        int d = __ldg(&dst[e]);
        float nm = g_norm[e];
        float4 v = *(const float4*)&g_xw1[(size_t)s * HH + lane * 4];
        float* p = &g_agg1[(size_t)d * HH + lane * 4];
        asm volatile("red.global.add.v4.f32 [%0], {%1,%2,%3,%4};"
                     :: "l"(p), "f"(nm * v.x), "f"(nm * v.y), "f"(nm * v.z), "f"(nm * v.w)
                     : "memory");
    }
}

// ---------------- layer-2 aggregation ----------------
__global__ void init_agg2_kernel(const float* __restrict__ b2) {
    int i = blockIdx.x * blockDim.x + threadIdx.x;     // float4 index
    if (i >= NN * (CC / 4)) return;
    int n = i / (CC / 4);
    int q = i % (CC / 4);
    float di = rsqrtf(g_deg[n]);
    float sc = di * di;
    float4 xv = ((const float4*)g_xw2)[i];
    float4 bv = __ldg(&((const float4*)b2)[q]);
    float4 o;
    o.x = sc * xv.x + bv.x; o.y = sc * xv.y + bv.y;
    o.z = sc * xv.z + bv.z; o.w = sc * xv.w + bv.w;
    ((float4*)g_agg2)[i] = o;
}

__global__ void scatter2_kernel(const int* __restrict__ src, const int* __restrict__ dst) {
    int gt = blockIdx.x * blockDim.x + threadIdx.x;
    int e = gt >> 2;          // 4 threads per edge (16 floats)
    int q = gt & 3;
    if (e >= EE) return;
    int s = __ldg(&src[e]);
    int d = __ldg(&dst[e]);
    float nm = g_norm[e];
    float4 v = ((const float4*)&g_xw2[(size_t)s * CC])[q];
    float* p = &g_agg2[(size_t)d * CC + q * 4];
    asm volatile("red.global.add.v4.f32 [%0], {%1,%2,%3,%4};"
                 :: "l"(p), "f"(nm * v.x), "f"(nm * v.y), "f"(nm * v.z), "f"(nm * v.w)
                 : "memory");
}

// ---------------- per-node: log_softmax, y_prob, u/v scalars ----------------
__global__ void node_kernel(const int* __restrict__ y, const void* __restrict__ tmask,
                            const float* __restrict__ Wd, float* __restrict__ out_lsm) {
    int n = blockIdx.x * blockDim.x + threadIdx.x;
    if (n >= NN) return;
    float l[CC];
    const float* lr = &g_agg2[(size_t)n * CC];
    float m = -1e30f;
#pragma unroll
    for (int c = 0; c < CC; c++) { l[c] = lr[c]; m = fmaxf(m, l[c]); }
    float se = 0.0f;
#pragma unroll
    for (int c = 0; c < CC; c++) se += expf(l[c] - m);
    float lse = logf(se);

    int kind = g_maskkind;
    bool msk;
    if (kind == 0)      msk = ((const int*)tmask)[n] != 0;
    else if (kind == 1) msk = ((const float*)tmask)[n] != 0.0f;
    else                msk = ((const unsigned char*)tmask)[n] != 0;
    int yc = y[n];

    float u = 0.0f, v = 0.0f;
#pragma unroll
    for (int c = 0; c < CC; c++) {
        float lsm = l[c] - m - lse;
        out_lsm[(size_t)n * CC + c] = lsm;
        float yp = msk ? ((c == yc) ? 1.0f : 0.0f) : expf(lsm);
        u += yp * __ldg(&Wd[128 + c]);
        v += yp * __ldg(&Wd[144 + c]);
    }
    const float4* xr = (const float4*)&g_xe[(size_t)n * HXD];
#pragma unroll
    for (int k4 = 0; k4 < HXD / 4; k4++) {
        float4 xv = xr[k4];
        int k = k4 * 4;
        u += xv.x * __ldg(&Wd[k + 0]) + xv.y * __ldg(&Wd[k + 1])
           + xv.z * __ldg(&Wd[k + 2]) + xv.w * __ldg(&Wd[k + 3]);
        v += xv.x * __ldg(&Wd[64 + k + 0]) + xv.y * __ldg(&Wd[64 + k + 1])
           + xv.z * __ldg(&Wd[64 + k + 2]) + xv.w * __ldg(&Wd[64 + k + 3]);
    }
    g_u[n] = u;
    g_v[n] = v;
}

// ---------------- edge decode ----------------
__global__ void decode_kernel(const int* __restrict__ pos, const int* __restrict__ neg,
                              const float* __restrict__ bd, float* __restrict__ out) {
    int i = blockIdx.x * blockDim.x + threadIdx.x;
    if (i >= 2 * EE) return;
    const int* ei = (i < EE) ? pos : neg;
    int k = (i < EE) ? i : i - EE;
    int s = ei[k];
    int d = ei[EE + k];
    out[i] = g_u[s] + g_v[d] + __ldg(bd);
}

// ---------------- launch ----------------
extern "C" void kernel_launch(void* const* d_in, const int* in_sizes, int n_in,
                              void* d_out, int out_size) {
    const float* x  = (const float*)d_in[0];
    const int* ei   = (const int*)d_in[1];   // [2, E] row-major: src then dst
    const int* nei  = (const int*)d_in[2];
    const int* y    = (const int*)d_in[3];
    const void* tm  = d_in[4];
    const float* W1 = (const float*)d_in[5];
    const float* b1 = (const float*)d_in[6];
    const float* W2 = (const float*)d_in[7];
    const float* b2 = (const float*)d_in[8];
    const float* Wx = (const float*)d_in[9];
    const float* bx = (const float*)d_in[10];
    const float* Wd = (const float*)d_in[11];
    const float* bd = (const float*)d_in[12];
    float* out = (float*)d_out;

    float *p_xw1, *p_xe, *p_agg1, *p_xw2;
    cudaGetSymbolAddress((void**)&p_xw1, g_xw1);
    cudaGetSymbolAddress((void**)&p_xe, g_xe);
    cudaGetSymbolAddress((void**)&p_agg1, g_agg1);
    cudaGetSymbolAddress((void**)&p_xw2, g_xw2);

    // side stream + events (created once, outside capture; fork/join is capture-legal)
    static cudaStream_t s1 = nullptr;
    static cudaEvent_t evFork = nullptr, evJoin = nullptr;
    if (!s1) {
        cudaStreamCreateWithFlags(&s1, cudaStreamNonBlocking);
        cudaEventCreateWithFlags(&evFork, cudaEventDisableTiming);
        cudaEventCreateWithFlags(&evJoin, cudaEventDisableTiming);
    }

    const int T = 256;

    prep_kernel<<<(NN + T - 1) / T, T>>>((const unsigned*)tm);
    cudaEventRecord(evFork, 0);
    cudaStreamWaitEvent(s1, evFork, 0);

    // side stream: degree, norm, xe-GEMM (independent of GEMM1; fills GEMM1's tail wave)
    deg_count_kernel<<<(EE + T - 1) / T, T, 0, s1>>>(ei + EE);
    norm_kernel<<<(EE + T - 1) / T, T, 0, s1>>>(ei, ei + EE);
    {   // xe = relu(x @ Wx + bx)
        dim3 grid(HXD / 64, (NN + 127) / 128);
        sgemm_kernel<128, 64, 16, 8, 4, false, 2><<<grid, 256, 0, s1>>>(x, Wx, bx, p_xe, NN, HXD, FF, 1);
    }
    cudaEventRecord(evJoin, s1);

    {   // xw1 = x @ W1 (bias deferred to init_agg1); 2 CTAs/SM, no frag double-buffer (no spill)
        dim3 grid(HH / 128, (NN + 127) / 128);
        sgemm_kernel<128, 128, 16, 8, 8, false, 2><<<grid, 256>>>(x, W1, nullptr, p_xw1, NN, HH, FF, 0);
    }
    cudaStreamWaitEvent(0, evJoin, 0);

    init_agg1_kernel<<<(NN * (HH / 4) + T - 1) / T, T>>>(b1);
    {   // layer-1 scatter: one warp per edge, 4 edges/warp
        int warps = (EE + 3) / 4;
        int blocks = (warps * 32 + T - 1) / T;
        scatter1_kernel<<<blocks, T>>>(ei, ei + EE);
    }

    {   // xw2 = relu(agg1) @ W2 — relu fused into A load
        dim3 grid(CC / 16, (NN + 127) / 128);
        sgemm_kernel<128, 16, 16, 8, 2, true, 2><<<grid, 128>>>(p_agg1, W2, nullptr, p_xw2, NN, CC, HH, 0);
    }
    init_agg2_kernel<<<(NN * (CC / 4) + T - 1) / T, T>>>(b2);
    scatter2_kernel<<<(EE * 4 + T - 1) / T, T>>>(ei, ei + EE);

    node_kernel<<<(NN + T - 1) / T, T>>>(y, tm, Wd, out + 2 * (size_t)EE);
    decode_kernel<<<(2 * EE + T - 1) / T, T>>>(ei, nei, bd, out);
}